// round 11
// baseline (speedup 1.0000x reference)
#include <cuda_runtime.h>
#include <cuda_fp16.h>
#include <math.h>

#define NN 100000
#define NPAD 100096            // 782 * 128
#define EE 1600000
#define HH 128
#define GG 1000
#define CC 10
#define NB_SCAN ((NN + 255) / 256)   // 391
#define KSTR 136               // smem W row stride in fp16 (272B, 16B-aligned)
#define ASTR 24                // smem A row stride in fp16 (48B: conflict-free ldsm)

// ---------------- scratch ----------------
__device__ __align__(16) __half g_hh[NN * HH];       // dinv-prescaled GEMM out (fp16)
__device__ __align__(16) __half g_a16[NPAD * HH];    // activations (fp16)
__device__ __align__(16) float g_dinv[NN];
__device__ __align__(16) int g_cnt[NN];
__device__ __align__(16) int g_rowptr[NN];
__device__ __align__(16) int g_fill[NN];
__device__ __align__(16) int g_bsum[NB_SCAN];
__device__ __align__(16) int g_boff[NB_SCAN];
__device__ __align__(16) int g_col[EE];
__device__ __align__(16) unsigned g_pool[GG * HH];

// ---------------- init (fused: pool + deg counters) ----------------
__global__ void init_all() {
    int j = blockIdx.x * blockDim.x + threadIdx.x;
    if (j < GG * HH) g_pool[j] = 0x007FFFFFu;  // enc(-inf)
    if (j < NN) g_cnt[j] = 0;
}
__global__ void deg_count(const int* __restrict__ ei) {
    int e = blockIdx.x * blockDim.x + threadIdx.x;
    if (e < EE) atomicAdd(&g_cnt[ei[EE + e]], 1);
}

// ---------------- exclusive scan (scan1 also emits dinv) ----------------
__global__ void scan1() {
    __shared__ int s[256];
    int tid = threadIdx.x;
    int i = blockIdx.x * 256 + tid;
    int v = (i < NN) ? g_cnt[i] : 0;
    if (i < NN) g_dinv[i] = rsqrtf(1.0f + (float)v);
    s[tid] = v;
    __syncthreads();
#pragma unroll
    for (int off = 1; off < 256; off <<= 1) {
        int t = (tid >= off) ? s[tid - off] : 0;
        __syncthreads();
        s[tid] += t;
        __syncthreads();
    }
    if (i < NN) g_rowptr[i] = s[tid] - v;
    if (tid == 255) g_bsum[blockIdx.x] = s[255];
}
__global__ void scan2() {
    __shared__ int s[512];
    int tid = threadIdx.x;
    int v = (tid < NB_SCAN) ? g_bsum[tid] : 0;
    s[tid] = v;
    __syncthreads();
#pragma unroll
    for (int off = 1; off < 512; off <<= 1) {
        int t = (tid >= off) ? s[tid - off] : 0;
        __syncthreads();
        s[tid] += t;
        __syncthreads();
    }
    if (tid < NB_SCAN) g_boff[tid] = s[tid] - v;
}
__global__ void scan3() {
    int i = blockIdx.x * blockDim.x + threadIdx.x;
    if (i < NN) {
        g_rowptr[i] += g_boff[i >> 8];
        g_fill[i] = 0;
    }
}
__global__ void csr_fill(const int* __restrict__ ei) {
    int e = blockIdx.x * blockDim.x + threadIdx.x;
    if (e < EE) {
        int s = ei[e];
        int d = ei[EE + e];
        int pos = g_rowptr[d] + atomicAdd(&g_fill[d], 1);
        g_col[pos] = s;
    }
}

// ---------------- x -> fp16 (covers padding) ----------------
__global__ void convert_x(const float* __restrict__ X) {
    int i = blockIdx.x * blockDim.x + threadIdx.x;  // over NPAD*64 float2
    if (i < NPAD * 64) {
        float2 v = (i < NN * 64) ? ((const float2*)X)[i] : make_float2(0.f, 0.f);
        ((__half2*)g_a16)[i] = __floats2half2_rn(v.x, v.y);
    }
}

// ---------------- tensor-core GEMM (fp16 single-term, cp.async A pipeline) -----
__device__ __forceinline__ void mma_f16(float c[4], unsigned a0, unsigned a1,
                                        unsigned a2, unsigned a3, unsigned b0,
                                        unsigned b1) {
    asm volatile(
        "mma.sync.aligned.m16n8k16.row.col.f32.f16.f16.f32 "
        "{%0,%1,%2,%3}, {%4,%5,%6,%7}, {%8,%9}, {%0,%1,%2,%3};"
        : "+f"(c[0]), "+f"(c[1]), "+f"(c[2]), "+f"(c[3])
        : "r"(a0), "r"(a1), "r"(a2), "r"(a3), "r"(b0), "r"(b1));
}
__device__ __forceinline__ void ldsm4t(unsigned& r0, unsigned& r1, unsigned& r2,
                                       unsigned& r3, unsigned saddr) {
    asm volatile(
        "ldmatrix.sync.aligned.m8n8.x4.trans.shared.b16 {%0,%1,%2,%3}, [%4];"
        : "=r"(r0), "=r"(r1), "=r"(r2), "=r"(r3)
        : "r"(saddr));
}
__device__ __forceinline__ void ldsm4(unsigned& r0, unsigned& r1, unsigned& r2,
                                      unsigned& r3, unsigned saddr) {
    asm volatile(
        "ldmatrix.sync.aligned.m8n8.x4.shared.b16 {%0,%1,%2,%3}, [%4];"
        : "=r"(r0), "=r"(r1), "=r"(r2), "=r"(r3)
        : "r"(saddr));
}

// stage one 128x16 fp16 A slab into smem buffer `buf` via cp.async (256 thr)
__device__ __forceinline__ void stageA(unsigned sa0, int buf, const __half* aP,
                                       int k0, int tid) {
    int row = tid >> 1;   // 0..127
    int half = tid & 1;   // k-halves 0-7 / 8-15
    const __half* src = aP + row * 128 + k0 + half * 8;
    unsigned dst = sa0 + ((unsigned)((buf * 128 + row) * ASTR + half * 8)) * 2;
    asm volatile("cp.async.cg.shared.global [%0], [%1], 16;\n" ::"r"(dst),
                 "l"(src));
}

__global__ __launch_bounds__(256, 2) void gemm_mma(const float* __restrict__ W) {
    extern __shared__ __half sw[];
    __half* Wh = sw;  // [128][KSTR]
    int tid = threadIdx.x;

    unsigned sbase = (unsigned)__cvta_generic_to_shared(sw);
    unsigned swh = sbase;
    unsigned sa0 = sbase + 128 * KSTR * 2;  // A region: [2 buf][128][ASTR]

    int row0 = blockIdx.x * 128;
    const __half* aP = g_a16 + (size_t)row0 * 128;

    stageA(sa0, 0, aP, 0, tid);
    asm volatile("cp.async.commit_group;\n");
    stageA(sa0, 1, aP, 16, tid);
    asm volatile("cp.async.commit_group;\n");

    for (int i = tid; i < 128 * 128; i += 256) {
        int k = i >> 7, n = i & 127;
        Wh[k * KSTR + n] = __float2half(W[i]);
    }
    __syncthreads();

    int warp = tid >> 5, lane = tid & 31;
    int g = lane >> 2, t = lane & 3;

    int q = lane >> 3, r = lane & 7;
    int kk_off = (r + ((q & 1) << 3)) * (KSTR * 2);
    int nn_off = ((q >> 1) << 3) * 2;

    unsigned aoff = ((unsigned)((warp * 16 + (lane & 15)) * ASTR + ((lane & 16) >> 1))) * 2;

    float c[16][4];
#pragma unroll
    for (int i = 0; i < 16; i++)
#pragma unroll
        for (int j = 0; j < 4; j++) c[i][j] = 0.f;

    for (int kb = 0; kb < 8; kb++) {
        if (kb < 7)
            asm volatile("cp.async.wait_group 1;\n");
        else
            asm volatile("cp.async.wait_group 0;\n");
        __syncthreads();

        int buf = kb & 1;
        unsigned ah0, ah1, ah2, ah3;
        ldsm4(ah0, ah1, ah2, ah3, sa0 + (unsigned)(buf * 128 * ASTR) * 2 + aoff);

        unsigned kbase = (unsigned)(kb * 16 * (KSTR * 2)) + kk_off + nn_off;
#pragma unroll
        for (int p = 0; p < 8; p++) {
            unsigned noff = kbase + p * 32;
            unsigned bh0, bh1, bh2, bh3;
            ldsm4t(bh0, bh1, bh2, bh3, swh + noff);
            mma_f16(c[2 * p],     ah0, ah1, ah2, ah3, bh0, bh1);
            mma_f16(c[2 * p + 1], ah0, ah1, ah2, ah3, bh2, bh3);
        }
        __syncthreads();
        if (kb < 6) {
            stageA(sa0, buf, aP, (kb + 2) * 16, tid);
            asm volatile("cp.async.commit_group;\n");
        }
    }

    int ra = row0 + warp * 16 + g, rb = ra + 8;
    float da = (ra < NN) ? g_dinv[ra] : 0.f;
    float db = (rb < NN) ? g_dinv[rb] : 0.f;
#pragma unroll
    for (int nt = 0; nt < 16; nt++) {
        int col = nt * 8 + t * 2;
        if (ra < NN)
            *(__half2*)&g_hh[(size_t)ra * 128 + col] =
                __floats2half2_rn(da * c[nt][0], da * c[nt][1]);
        if (rb < NN)
            *(__half2*)&g_hh[(size_t)rb * 128 + col] =
                __floats2half2_rn(db * c[nt][2], db * c[nt][3]);
    }
}

// ---------------- pool encode ----------------
__device__ __forceinline__ unsigned enc_f(float x) {
    unsigned u = __float_as_uint(x);
    return (u & 0x80000000u) ? ~u : (u | 0x80000000u);
}
__device__ __forceinline__ float dec_f(unsigned e) {
    return (e & 0x80000000u) ? __uint_as_float(e ^ 0x80000000u)
                             : __uint_as_float(~e);
}

// ---------------- fused gather: half-warp per neighbor, LDG.128, HADD2 --------
// warp = dst node. lanes 0-15 process even neighbors, 16-31 odd neighbors.
// lane owns 8 features (uint4 = 8 halves); cross-half combine at the end.
__global__ void gather_fused(const float* __restrict__ bias,
                             const int* __restrict__ batch, int do_pool) {
    int warp = (blockIdx.x * blockDim.x + threadIdx.x) >> 5;
    int lane = threadIdx.x & 31;
    if (warp >= NN) return;
    int d = warp;
    int beg = g_rowptr[d];
    int n_all = g_cnt[d];
    int half = lane >> 4;   // 0 or 1
    int fl = lane & 15;     // feature slot: 8 features each
    const uint4* h4 = (const uint4*)g_hh;  // 16 uint4 per 128-half row

    __half2 z = __float2half2_rn(0.f);
    __half2 acc0 = z, acc1 = z, acc2 = z, acc3 = z;

    for (int base = 0; base < n_all; base += 32) {
        int n = min(32, n_all - base);
        int c = (lane < n) ? g_col[beg + base + lane] : 0;
        for (int j = 0; j < n; j += 4) {
            int j0 = j + half;
            int j1 = j + 2 + half;
            int s0 = __shfl_sync(0xffffffffu, c, j0 & 31);
            int s1 = __shfl_sync(0xffffffffu, c, j1 & 31);
            bool v0 = j0 < n, v1 = j1 < n;
            uint4 A, B;
            if (v0) A = h4[(size_t)s0 * 16 + fl];
            if (v1) B = h4[(size_t)s1 * 16 + fl];
            if (v0) {
                acc0 = __hadd2(acc0, *(__half2*)&A.x);
                acc1 = __hadd2(acc1, *(__half2*)&A.y);
                acc2 = __hadd2(acc2, *(__half2*)&A.z);
                acc3 = __hadd2(acc3, *(__half2*)&A.w);
            }
            if (v1) {
                acc0 = __hadd2(acc0, *(__half2*)&B.x);
                acc1 = __hadd2(acc1, *(__half2*)&B.y);
                acc2 = __hadd2(acc2, *(__half2*)&B.z);
                acc3 = __hadd2(acc3, *(__half2*)&B.w);
            }
        }
    }
    // combine even/odd neighbor halves (lanes fl and fl+16 hold same features)
    acc0 = __hadd2(acc0, __shfl_xor_sync(0xffffffffu, acc0, 16));
    acc1 = __hadd2(acc1, __shfl_xor_sync(0xffffffffu, acc1, 16));
    acc2 = __hadd2(acc2, __shfl_xor_sync(0xffffffffu, acc2, 16));
    acc3 = __hadd2(acc3, __shfl_xor_sync(0xffffffffu, acc3, 16));

    // epilogue: each lane finishes 4 features: f0 = fl*8 + half*4
    int f0 = fl * 8 + half * 4;
    float2 a01, a23;
    if (half == 0) {
        a01 = __half22float2(acc0);
        a23 = __half22float2(acc1);
    } else {
        a01 = __half22float2(acc2);
        a23 = __half22float2(acc3);
    }
    float dd = g_dinv[d];
    const uint2* h2 = (const uint2*)g_hh;
    uint2 hsv = h2[(size_t)d * 32 + fl * 2 + half];  // own features f0..f0+3
    float2 s0 = __half22float2(*(__half2*)&hsv.x);
    float2 s1 = __half22float2(*(__half2*)&hsv.y);
    float4 bb = *(const float4*)&bias[f0];
    float vx = dd * (a01.x + s0.x) + bb.x;
    float vy = dd * (a01.y + s0.y) + bb.y;
    float vz = dd * (a23.x + s1.x) + bb.z;
    float vw = dd * (a23.y + s1.y) + bb.w;
    vx = vx > 0.f ? vx : expm1f(vx);
    vy = vy > 0.f ? vy : expm1f(vy);
    vz = vz > 0.f ? vz : expm1f(vz);
    vw = vw > 0.f ? vw : expm1f(vw);

    if (!do_pool) {
        __half2* pa = (__half2*)g_a16 + (size_t)d * 64 + f0 / 2;
        pa[0] = __floats2half2_rn(vx, vy);
        pa[1] = __floats2half2_rn(vz, vw);
    } else {
        int g = batch[d];
        unsigned* p = &g_pool[g * 128 + f0];
        atomicMax(&p[0], enc_f(vx));
        atomicMax(&p[1], enc_f(vy));
        atomicMax(&p[2], enc_f(vz));
        atomicMax(&p[3], enc_f(vw));
    }
}

// ---------------- head ----------------
__global__ void head(const float* __restrict__ Wl, const float* __restrict__ bl,
                     float* __restrict__ out) {
    int warp = (blockIdx.x * blockDim.x + threadIdx.x) >> 5;
    int lane = threadIdx.x & 31;
    if (warp >= GG) return;
    float part[CC];
#pragma unroll
    for (int c = 0; c < CC; c++) part[c] = 0.f;
    for (int f = lane; f < HH; f += 32) {
        float p = dec_f(g_pool[warp * HH + f]);
        if (p < -3.0e38f) p = 0.0f;
#pragma unroll
        for (int c = 0; c < CC; c++) part[c] += p * Wl[f * CC + c];
    }
#pragma unroll
    for (int c = 0; c < CC; c++)
        for (int off = 16; off; off >>= 1)
            part[c] += __shfl_xor_sync(0xffffffffu, part[c], off);
    if (lane == 0) {
        float lg[CC];
        float m = -3.4e38f;
#pragma unroll
        for (int c = 0; c < CC; c++) {
            lg[c] = part[c] + bl[c];
            m = fmaxf(m, lg[c]);
        }
        float sum = 0.f;
#pragma unroll
        for (int c = 0; c < CC; c++) {
            lg[c] = expf(lg[c] - m);
            sum += lg[c];
        }
        float inv = 1.0f / sum;
#pragma unroll
        for (int c = 0; c < CC; c++) out[warp * CC + c] = lg[c] * inv;
    }
}

// ---------------- launcher ----------------
extern "C" void kernel_launch(void* const* d_in, const int* in_sizes, int n_in,
                              void* d_out, int out_size) {
    const float* x = (const float*)d_in[0];
    const int* ei = (const int*)d_in[1];
    const int* batch = (const int*)d_in[2];
    const float* W0 = (const float*)d_in[3];
    const float* b0 = (const float*)d_in[4];
    const float* W1 = (const float*)d_in[5];
    const float* b1 = (const float*)d_in[6];
    const float* W2 = (const float*)d_in[7];
    const float* b2 = (const float*)d_in[8];
    const float* Wl = (const float*)d_in[9];
    const float* bl = (const float*)d_in[10];
    float* out = (float*)d_out;

    const int T = 256;
    const int gemm_smem = 128 * KSTR * 2 + 2 * 128 * ASTR * 2;  // 47104 B
    cudaFuncSetAttribute(gemm_mma, cudaFuncAttributeMaxDynamicSharedMemorySize,
                         gemm_smem);

    init_all<<<(GG * HH + T - 1) / T, T>>>();
    deg_count<<<(EE + T - 1) / T, T>>>(ei);
    scan1<<<NB_SCAN, 256>>>();
    scan2<<<1, 512>>>();
    scan3<<<(NN + T - 1) / T, T>>>();
    csr_fill<<<(EE + T - 1) / T, T>>>(ei);
    convert_x<<<(NPAD * 64 + T - 1) / T, T>>>(x);

    const int gemm_blocks = NPAD / 128;  // 782
    const int gather_blocks = (NN * 32 + T - 1) / T;

    const float* Ws[3] = {W0, W1, W2};
    const float* bs[3] = {b0, b1, b2};
    for (int l = 0; l < 3; l++) {
        gemm_mma<<<gemm_blocks, T, gemm_smem>>>(Ws[l]);
        gather_fused<<<gather_blocks, T>>>(bs[l], batch, l == 2 ? 1 : 0);
    }

    head<<<(GG + 7) / 8, T>>>(Wl, bl, out);
}